// round 9
// baseline (speedup 1.0000x reference)
#include <cuda_runtime.h>

#define NU 50000
#define NI 100000
#define NN 150000
#define NE 2400000
#define N_LAYERS 3
#define KE 64  // edges per warp in segmented spmm (NE % KE == 0)

// ---- scratch (device globals; no allocation) ----
// g_side: zero at load; dense re-zeroes the rows it consumes each layer.
// g_cnt: zero at load; zero_cnt re-zeroes it each call (after scan reads it).
__device__ float g_ego0[NN * 64];
__device__ float g_ego1[NN * 64];
__device__ float g_side[NN * 64];
__device__ int g_cnt[NN];  // histogram (always returned to zero)
__device__ int g_cur[NN];  // scatter cursors
// packed edge, dst-sorted: bits[36:64)=val(f32>>4), [18:36)=dst, [0:18)=src
__device__ unsigned long long g_edges[NE];

// ---------------------------------------------------------------------------
// init + hist fused: NN*16 threads == NE threads exactly.
// ---------------------------------------------------------------------------
__global__ void init_hist_kernel(const float4* __restrict__ ue,
                                 const float4* __restrict__ ie,
                                 float4* __restrict__ out4,
                                 const int* __restrict__ edst) {
    int idx = blockIdx.x * blockDim.x + threadIdx.x;
    if (idx >= NE) return;  // NE == NN*16
    atomicAdd(&g_cnt[edst[idx]], 1);
    int row = idx >> 4;
    int c = idx & 15;
    float4 v = (row < NU) ? ue[row * 16 + c] : ie[(row - NU) * 16 + c];
    ((float4*)g_ego0)[idx] = v;
    out4[row * 64 + c] = v;
}

// ---------------------------------------------------------------------------
// scan: prefix of g_cnt -> g_cur cursors.
// ---------------------------------------------------------------------------
__global__ void scan_kernel() {  // <<<1, 1024>>>
    __shared__ int part[1024];
    int t = threadIdx.x;
    const int CH = (NN + 1023) / 1024;  // 147
    int beg = t * CH;
    int end = min(beg + CH, NN);
    int s = 0;
    for (int i0 = beg; i0 < end; i0 += 8) {
        int c[8];
#pragma unroll
        for (int u = 0; u < 8; u++)
            c[u] = (i0 + u < end) ? g_cnt[i0 + u] : 0;
#pragma unroll
        for (int u = 0; u < 8; u++) s += c[u];
    }
    part[t] = s;
    __syncthreads();
    for (int o = 1; o < 1024; o <<= 1) {
        int v = (t >= o) ? part[t - o] : 0;
        __syncthreads();
        part[t] += v;
        __syncthreads();
    }
    int pre = (t == 0) ? 0 : part[t - 1];
    for (int i0 = beg; i0 < end; i0 += 8) {
        int c[8];
#pragma unroll
        for (int u = 0; u < 8; u++)
            c[u] = (i0 + u < end) ? g_cnt[i0 + u] : 0;
#pragma unroll
        for (int u = 0; u < 8; u++) {
            if (i0 + u < end) {
                g_cur[i0 + u] = pre;
                pre += c[u];
            }
        }
    }
}

// restore g_cnt==0 invariant for next graph replay (also shifts ncu capture)
__global__ void zero_cnt_kernel() {
    int i = blockIdx.x * blockDim.x + threadIdx.x;
    if (i < NN) g_cnt[i] = 0;
}

__global__ void scatter_kernel(const int* __restrict__ esrc,
                               const int* __restrict__ edst,
                               const float* __restrict__ ev) {
    int e = blockIdx.x * blockDim.x + threadIdx.x;
    if (e >= NE) return;
    int d = edst[e];
    int pos = atomicAdd(&g_cur[d], 1);
    unsigned vb = __float_as_uint(ev[e]);
    g_edges[pos] = ((unsigned long long)(vb >> 4) << 36) |
                   ((unsigned long long)(unsigned)d << 18) |
                   (unsigned long long)(unsigned)esrc[e];
}

// ---------------------------------------------------------------------------
// segmented-reduction SpMM (unchanged from R8: near its L2 floor)
// ---------------------------------------------------------------------------
__device__ __forceinline__ void flush4(int row, int l16, float4 a) {
    float* p = g_side + (size_t)row * 64 + l16 * 4;
    asm volatile("red.global.add.v4.f32 [%0], {%1,%2,%3,%4};"
                 :: "l"(p), "f"(a.x), "f"(a.y), "f"(a.z), "f"(a.w)
                 : "memory");
}

__global__ void __launch_bounds__(256, 3) spmm_kernel(
    const float* __restrict__ egoIn) {
    int gw = (blockIdx.x * blockDim.x + threadIdx.x) >> 5;
    if (gw >= NE / KE) return;
    int lane = threadIdx.x & 31;
    int h = lane >> 4;
    int l16 = lane & 15;
    const float4* ego4 = (const float4*)egoIn;
    const ulonglong2* ep = (const ulonglong2*)(g_edges + (size_t)gw * KE);

    unsigned long long my[8];
#pragma unroll
    for (int u = 0; u < 8; u++) {
        ulonglong2 p = __ldg(ep + u);
        my[u] = h ? p.y : p.x;
    }
    float4 acc = make_float4(0.f, 0.f, 0.f, 0.f);
    int cur = (int)((my[0] >> 18) & 0x3FFFFu);

#pragma unroll
    for (int j = 0; j < KE / 16; j++) {
        float4 x[8];
#pragma unroll
        for (int u = 0; u < 8; u++) {
            unsigned src = (unsigned)my[u] & 0x3FFFFu;
            x[u] = __ldcg(&ego4[(size_t)src * 16 + l16]);
        }
        unsigned long long nxt[8];
        if (j < KE / 16 - 1) {
#pragma unroll
            for (int u = 0; u < 8; u++) {
                ulonglong2 p = __ldg(ep + (j + 1) * 8 + u);
                nxt[u] = h ? p.y : p.x;
            }
        }
#pragma unroll
        for (int u = 0; u < 8; u++) {
            int d = (int)((my[u] >> 18) & 0x3FFFFu);
            if (d != cur) {
                flush4(cur, l16, acc);
                acc = make_float4(0.f, 0.f, 0.f, 0.f);
                cur = d;
            }
            float v = __uint_as_float((unsigned)(my[u] >> 36) << 4);
            acc.x = fmaf(v, x[u].x, acc.x);
            acc.y = fmaf(v, x[u].y, acc.y);
            acc.z = fmaf(v, x[u].z, acc.z);
            acc.w = fmaf(v, x[u].w, acc.w);
        }
        if (j < KE / 16 - 1) {
#pragma unroll
            for (int u = 0; u < 8; u++) my[u] = nxt[u];
        }
    }
    flush4(cur, l16, acc);
}

// ---------------------------------------------------------------------------
// packed f32x2 helpers
// ---------------------------------------------------------------------------
__device__ __forceinline__ unsigned long long pack2(float x) {
    unsigned long long r;
    asm("mov.b64 %0, {%1,%1};" : "=l"(r) : "f"(x));
    return r;
}
__device__ __forceinline__ void ffma2(unsigned long long& d,
                                      unsigned long long a,
                                      unsigned long long b) {
    asm("fma.rn.f32x2 %0, %1, %2, %0;" : "+l"(d) : "l"(a), "l"(b));
}
__device__ __forceinline__ float2 unpack2(unsigned long long v) {
    float2 f;
    asm("mov.b64 {%0,%1}, %2;" : "=f"(f.x), "=f"(f.y) : "l"(v));
    return f;
}

// ---------------------------------------------------------------------------
// dense layer, 512 threads / 128-row tile (thread tile 4 rows x 4 cols x 2).
// 32 warps/SM at occ 2 -> fill/epilogue latency hidden across CTAs.
// ---------------------------------------------------------------------------
__global__ void __launch_bounds__(512, 2) dense_kernel(
    const float* __restrict__ Wgc, const float* __restrict__ bgc,
    const float* __restrict__ Wbi, const float* __restrict__ bbi,
    const float* __restrict__ egoIn, float* __restrict__ egoOut,
    int layer, float* __restrict__ out) {
    extern __shared__ float sm[];
    float* sX = sm;               // side  [128][64]
    float* sP = sm + 8192;        // ego*side [128][64]
    float* sWg = sm + 16384;      // Wgc^T [k][j]
    float* sWb = sWg + 4096;      // Wbi^T

    const float* Wg = Wgc + layer * 4096;
    const float* Wb = Wbi + layer * 4096;
    int tid = threadIdx.x;
    int row0 = blockIdx.x * 128;

    // W transpose fill: lane j varies fastest -> conflict-free STS
    for (int idx = tid; idx < 1024; idx += 512) {
        int j = idx & 63;
        int k4 = (idx >> 6) << 2;
        float4 wg = __ldg((const float4*)(Wg + j * 64 + k4));
        float4 wb = __ldg((const float4*)(Wb + j * 64 + k4));
        sWg[(k4 + 0) * 64 + j] = wg.x;
        sWg[(k4 + 1) * 64 + j] = wg.y;
        sWg[(k4 + 2) * 64 + j] = wg.z;
        sWg[(k4 + 3) * 64 + j] = wg.w;
        sWb[(k4 + 0) * 64 + j] = wb.x;
        sWb[(k4 + 1) * 64 + j] = wb.y;
        sWb[(k4 + 2) * 64 + j] = wb.z;
        sWb[(k4 + 3) * 64 + j] = wb.w;
    }
    for (int idx = tid; idx < 2048; idx += 512) {
        int r = idx >> 4;
        int c = idx & 15;
        int row = row0 + r;
        float4 xs = make_float4(0.f, 0.f, 0.f, 0.f);
        float4 xe = xs;
        if (row < NN) {
            xs = __ldg(&((const float4*)g_side)[row * 16 + c]);
            xe = __ldg(&((const float4*)egoIn)[row * 16 + c]);
        }
        *(float4*)(sX + r * 64 + c * 4) = xs;
        *(float4*)(sP + r * 64 + c * 4) =
            make_float4(xs.x * xe.x, xs.y * xe.y, xs.z * xe.z, xs.w * xe.w);
    }
    __syncthreads();

    // re-zero this block's side rows for the next spmm (fused memset)
    {
        float4 z = make_float4(0.f, 0.f, 0.f, 0.f);
        for (int idx = tid; idx < 2048; idx += 512) {
            int r = idx >> 4;
            int c = idx & 15;
            int row = row0 + r;
            if (row < NN) ((float4*)g_side)[row * 16 + c] = z;
        }
    }

    int tx = tid & 15;   // cols tx*4 .. tx*4+3
    int ty = tid >> 4;   // rows ty*4 .. ty*4+3 (ty in 0..31)

    unsigned long long ag[4][2], ab[4][2];
#pragma unroll
    for (int i = 0; i < 4; i++) {
        ag[i][0] = 0ull; ag[i][1] = 0ull;
        ab[i][0] = 0ull; ab[i][1] = 0ull;
    }

#pragma unroll 4
    for (int k = 0; k < 64; k += 2) {
        ulonglong2 wg0 = *(const ulonglong2*)(sWg + k * 64 + tx * 4);
        ulonglong2 wb0 = *(const ulonglong2*)(sWb + k * 64 + tx * 4);
        ulonglong2 wg1 = *(const ulonglong2*)(sWg + (k + 1) * 64 + tx * 4);
        ulonglong2 wb1 = *(const ulonglong2*)(sWb + (k + 1) * 64 + tx * 4);
#pragma unroll
        for (int i = 0; i < 4; i++) {
            int r = ty * 4 + i;
            float2 xs = *(const float2*)(sX + r * 64 + k);
            float2 xp = *(const float2*)(sP + r * 64 + k);
            unsigned long long a0 = pack2(xs.x);
            unsigned long long a1 = pack2(xs.y);
            unsigned long long b0 = pack2(xp.x);
            unsigned long long b1 = pack2(xp.y);
            ffma2(ag[i][0], a0, wg0.x);
            ffma2(ag[i][1], a0, wg0.y);
            ffma2(ab[i][0], b0, wb0.x);
            ffma2(ab[i][1], b0, wb0.y);
            ffma2(ag[i][0], a1, wg1.x);
            ffma2(ag[i][1], a1, wg1.y);
            ffma2(ab[i][0], b1, wb1.x);
            ffma2(ab[i][1], b1, wb1.y);
        }
    }

    float4 bg = *(const float4*)(bgc + layer * 64 + tx * 4);
    float4 bb = *(const float4*)(bbi + layer * 64 + tx * 4);
    const float bgv[4] = {bg.x, bg.y, bg.z, bg.w};
    const float bbv[4] = {bb.x, bb.y, bb.z, bb.w};

    int colbase = (layer + 1) * 64 + tx * 4;
#pragma unroll
    for (int i = 0; i < 4; i++) {
        int row = row0 + ty * 4 + i;
        float2 g0 = unpack2(ag[i][0]);
        float2 g1 = unpack2(ag[i][1]);
        float2 b0 = unpack2(ab[i][0]);
        float2 b1 = unpack2(ab[i][1]);
        float gv[4] = {g0.x, g0.y, g1.x, g1.y};
        float bv[4] = {b0.x, b0.y, b1.x, b1.y};
        float v[4];
        float ss = 0.f;
#pragma unroll
        for (int c = 0; c < 4; c++) {
            float s = gv[c] + bgv[c];
            s = (s > 0.f) ? s : 0.01f * s;
            float b = bv[c] + bbv[c];
            b = (b > 0.f) ? b : 0.01f * b;
            v[c] = s + b;
            ss += v[c] * v[c];
        }
#pragma unroll
        for (int o = 8; o > 0; o >>= 1)
            ss += __shfl_xor_sync(0xffffffffu, ss, o, 16);
        float inv = 1.0f / fmaxf(sqrtf(ss), 1e-12f);
        if (row < NN) {
            ((float4*)egoOut)[row * 16 + tx] =
                make_float4(v[0], v[1], v[2], v[3]);
            *(float4*)(out + (size_t)row * 256 + colbase) =
                make_float4(v[0] * inv, v[1] * inv, v[2] * inv, v[3] * inv);
        }
    }
}

// ---------------------------------------------------------------------------
extern "C" void kernel_launch(void* const* d_in, const int* in_sizes, int n_in,
                              void* d_out, int out_size) {
    const int* esrc = (const int*)d_in[0];
    const int* edst = (const int*)d_in[1];
    const float* ev = (const float*)d_in[2];
    const float* ue = (const float*)d_in[3];
    const float* ie = (const float*)d_in[4];
    const float* Wgc = (const float*)d_in[5];
    const float* bgc = (const float*)d_in[6];
    const float* Wbi = (const float*)d_in[7];
    const float* bbi = (const float*)d_in[8];
    float* out = (float*)d_out;

    void* e0 = nullptr;
    void* e1 = nullptr;
    cudaGetSymbolAddress(&e0, g_ego0);
    cudaGetSymbolAddress(&e1, g_ego1);
    float* bufs[2] = {(float*)e0, (float*)e1};

    cudaFuncSetAttribute(dense_kernel,
                         cudaFuncAttributeMaxDynamicSharedMemorySize, 98304);

    // 1) ego init + out slice 0 + edge histogram (fused)
    init_hist_kernel<<<(NE + 255) / 256, 256>>>(
        (const float4*)ue, (const float4*)ie, (float4*)out, edst);
    // 2) prefix -> cursors
    scan_kernel<<<1, 1024>>>();
    // 3) restore g_cnt zero invariant
    zero_cnt_kernel<<<(NN + 255) / 256, 256>>>();
    // 4) dst-sorted packed edge list
    scatter_kernel<<<(NE + 255) / 256, 256>>>(esrc, edst, ev);

    int sgrid = (NE / KE * 32 + 255) / 256;  // warp per KE-edge chunk
    int dgrid = (NN + 127) / 128;
    for (int l = 0; l < N_LAYERS; l++) {
        spmm_kernel<<<sgrid, 256>>>(bufs[l & 1]);  // launch 5 (+2l)
        dense_kernel<<<dgrid, 512, 98304>>>(Wgc, bgc, Wbi, bbi,   // launch 6
                                            bufs[l & 1], bufs[(l + 1) & 1],
                                            l, out);
    }
}